// round 1
// baseline (speedup 1.0000x reference)
#include <cuda_runtime.h>
#include <math.h>

#define S_LEN 2048
#define DM    1024
#define NH    16
#define HD    64
#define BATCH 2
#define BHN   (BATCH * NH)        // 32
#define MROWS (BATCH * S_LEN)     // 4096

// Scratch (alloc-free rule: __device__ globals). 4 x 16 MB.
__device__ float g_Q[(size_t)BHN * S_LEN * HD];
__device__ float g_K[(size_t)BHN * S_LEN * HD];
__device__ float g_V[(size_t)BHN * S_LEN * HD];
__device__ float g_A[(size_t)MROWS * DM];

// ---------------------------------------------------------------------------
// C[r,e] = sum_d A[r,d] * W[e,d] + bias[e]    (M=4096, N=1024, K=1024)
// reorder=1: write to [B,H,S,Hd] layout (for Q/K/V). reorder=0: row-major.
// Tile 64x64x16, 256 threads, 4x4 per thread.
// ---------------------------------------------------------------------------
__global__ void proj_kernel(const float* __restrict__ A,
                            const float* __restrict__ W,
                            const float* __restrict__ bias,
                            float* __restrict__ out, int reorder)
{
    __shared__ float As[16][64];
    __shared__ float Bs[16][64];
    const int tid = threadIdx.x;
    const int tx = tid & 15, ty = tid >> 4;
    const int r0 = blockIdx.y * 64;
    const int c0 = blockIdx.x * 64;
    float acc[4][4] = {};
    for (int k0 = 0; k0 < DM; k0 += 16) {
#pragma unroll
        for (int i = 0; i < 4; i++) {
            int e   = tid + i * 256;
            int row = e >> 4, col = e & 15;
            As[col][row] = A[(size_t)(r0 + row) * DM + k0 + col];
            Bs[col][row] = W[(size_t)(c0 + row) * DM + k0 + col];
        }
        __syncthreads();
#pragma unroll
        for (int k = 0; k < 16; k++) {
            float a[4], b[4];
#pragma unroll
            for (int i = 0; i < 4; i++) a[i] = As[k][ty * 4 + i];
#pragma unroll
            for (int j = 0; j < 4; j++) b[j] = Bs[k][tx * 4 + j];
#pragma unroll
            for (int i = 0; i < 4; i++)
#pragma unroll
                for (int j = 0; j < 4; j++)
                    acc[i][j] = fmaf(a[i], b[j], acc[i][j]);
        }
        __syncthreads();
    }
#pragma unroll
    for (int i = 0; i < 4; i++) {
        int r = r0 + ty * 4 + i;
#pragma unroll
        for (int j = 0; j < 4; j++) {
            int e = c0 + tx * 4 + j;
            float v = acc[i][j] + bias[e];
            if (reorder) {
                int bb = r >> 11, s = r & (S_LEN - 1);
                int h = e >> 6, hd = e & 63;
                out[((size_t)(bb * NH + h) * S_LEN + s) * HD + hd] = v;
            } else {
                out[(size_t)r * DM + e] = v;
            }
        }
    }
}

// ---------------------------------------------------------------------------
// scores[bh,q,k] = 0.125 * sum_hd Q[bh,q,hd]*K[bh,k,hd]; skip kt > qt tiles.
// ---------------------------------------------------------------------------
__global__ void scores_kernel(const float* __restrict__ Q,
                              const float* __restrict__ K,
                              float* __restrict__ attn)
{
    const int kt = blockIdx.x, qt = blockIdx.y, bh = blockIdx.z;
    if (kt > qt) return;
    const float* Qb = Q + (size_t)bh * S_LEN * HD;
    const float* Kb = K + (size_t)bh * S_LEN * HD;
    float* Ab = attn + (size_t)bh * S_LEN * S_LEN;

    __shared__ float Qs[16][64];
    __shared__ float Ks[16][64];
    const int tid = threadIdx.x;
    const int tx = tid & 15, ty = tid >> 4;
    const int q0 = qt * 64, c0 = kt * 64;
    float acc[4][4] = {};
    for (int k0 = 0; k0 < HD; k0 += 16) {
#pragma unroll
        for (int i = 0; i < 4; i++) {
            int e   = tid + i * 256;
            int row = e >> 4, col = e & 15;
            Qs[col][row] = Qb[(size_t)(q0 + row) * HD + k0 + col];
            Ks[col][row] = Kb[(size_t)(c0 + row) * HD + k0 + col];
        }
        __syncthreads();
#pragma unroll
        for (int k = 0; k < 16; k++) {
            float a[4], b[4];
#pragma unroll
            for (int i = 0; i < 4; i++) a[i] = Qs[k][ty * 4 + i];
#pragma unroll
            for (int j = 0; j < 4; j++) b[j] = Ks[k][tx * 4 + j];
#pragma unroll
            for (int i = 0; i < 4; i++)
#pragma unroll
                for (int j = 0; j < 4; j++)
                    acc[i][j] = fmaf(a[i], b[j], acc[i][j]);
        }
        __syncthreads();
    }
#pragma unroll
    for (int i = 0; i < 4; i++)
#pragma unroll
        for (int j = 0; j < 4; j++)
            Ab[(size_t)(q0 + ty * 4 + i) * S_LEN + c0 + tx * 4 + j] =
                acc[i][j] * 0.125f;
}

// ---------------------------------------------------------------------------
// Row-wise causal softmax in place. One block (256 thr) per row; 8 vals/thread.
// Writes zeros for k > q (d_out is poisoned, every byte must be written).
// ---------------------------------------------------------------------------
__global__ void softmax_kernel(float* __restrict__ attn)
{
    const int q = blockIdx.x, bh = blockIdx.y;
    float* row = attn + ((size_t)bh * S_LEN + q) * S_LEN;
    const int tid = threadIdx.x;
    const int valid = q + 1;

    float vals[8];
    float mx = -INFINITY;
#pragma unroll
    for (int i = 0; i < 8; i++) {
        int k = tid + i * 256;
        float v = (k < valid) ? row[k] : -INFINITY;
        vals[i] = v;
        mx = fmaxf(mx, v);
    }
    __shared__ float red[256];
    red[tid] = mx;
    __syncthreads();
    for (int s = 128; s > 0; s >>= 1) {
        if (tid < s) red[tid] = fmaxf(red[tid], red[tid + s]);
        __syncthreads();
    }
    mx = red[0];
    __syncthreads();

    float sum = 0.f;
#pragma unroll
    for (int i = 0; i < 8; i++) {
        int k = tid + i * 256;
        float e = (k < valid) ? __expf(vals[i] - mx) : 0.f;
        vals[i] = e;
        sum += e;
    }
    red[tid] = sum;
    __syncthreads();
    for (int s = 128; s > 0; s >>= 1) {
        if (tid < s) red[tid] += red[tid + s];
        __syncthreads();
    }
    const float inv = 1.f / red[0];
#pragma unroll
    for (int i = 0; i < 8; i++) {
        int k = tid + i * 256;
        row[k] = vals[i] * inv;
    }
}

// ---------------------------------------------------------------------------
// A[bh,q,hd] = sum_k attn[bh,q,k] * V[bh,k,hd], causal k bound; write [B,S,D].
// Tile 64x64(full N)x32.
// ---------------------------------------------------------------------------
__global__ void av_kernel(const float* __restrict__ attn,
                          const float* __restrict__ V,
                          float* __restrict__ Aout)
{
    const int qt = blockIdx.x, bh = blockIdx.z;
    const int q0 = qt * 64;
    const float* Pb = attn + (size_t)bh * S_LEN * S_LEN;
    const float* Vb = V + (size_t)bh * S_LEN * HD;

    __shared__ float Ps[32][64];
    __shared__ float Vs[32][64];
    const int tid = threadIdx.x;
    const int tx = tid & 15, ty = tid >> 4;
    const int kend = q0 + 64;  // rows in this tile have zero attn beyond q0+63
    float acc[4][4] = {};
    for (int k0 = 0; k0 < kend; k0 += 32) {
#pragma unroll
        for (int i = 0; i < 8; i++) {
            int e = tid + i * 256;
            {   // P tile: 64 rows x 32 cols
                int row = e >> 5, col = e & 31;
                Ps[col][row] = Pb[(size_t)(q0 + row) * S_LEN + k0 + col];
            }
            {   // V tile: 32 rows x 64 cols
                int row = e >> 6, col = e & 63;
                Vs[row][col] = Vb[(size_t)(k0 + row) * HD + col];
            }
        }
        __syncthreads();
#pragma unroll
        for (int k = 0; k < 32; k++) {
            float a[4], b[4];
#pragma unroll
            for (int i = 0; i < 4; i++) a[i] = Ps[k][ty * 4 + i];
#pragma unroll
            for (int j = 0; j < 4; j++) b[j] = Vs[k][tx * 4 + j];
#pragma unroll
            for (int i = 0; i < 4; i++)
#pragma unroll
                for (int j = 0; j < 4; j++)
                    acc[i][j] = fmaf(a[i], b[j], acc[i][j]);
        }
        __syncthreads();
    }
    const int bb = bh / NH, h = bh % NH;
#pragma unroll
    for (int i = 0; i < 4; i++) {
        int s = q0 + ty * 4 + i;
#pragma unroll
        for (int j = 0; j < 4; j++) {
            int hd = tx * 4 + j;
            Aout[(size_t)(bb * S_LEN + s) * DM + h * HD + hd] = acc[i][j];
        }
    }
}

// ---------------------------------------------------------------------------
extern "C" void kernel_launch(void* const* d_in, const int* in_sizes, int n_in,
                              void* d_out, int out_size)
{
    const float* X  = (const float*)d_in[0];
    const float* Wq = (const float*)d_in[1];
    const float* bq = (const float*)d_in[2];
    const float* Wk = (const float*)d_in[3];
    const float* bk = (const float*)d_in[4];
    const float* Wv = (const float*)d_in[5];
    const float* bv = (const float*)d_in[6];
    const float* Wo = (const float*)d_in[7];
    const float* bo = (const float*)d_in[8];

    float* out  = (float*)d_out;
    // Output layout: flattened (out [B,S,D], attn [B,H,S,S])
    float* attn = out + (size_t)MROWS * DM;

    float *gQ, *gK, *gV, *gA;
    cudaGetSymbolAddress((void**)&gQ, g_Q);
    cudaGetSymbolAddress((void**)&gK, g_K);
    cudaGetSymbolAddress((void**)&gV, g_V);
    cudaGetSymbolAddress((void**)&gA, g_A);

    dim3 blk(256);
    dim3 gproj(DM / 64, MROWS / 64);          // (16, 64)
    proj_kernel<<<gproj, blk>>>(X, Wq, bq, gQ, 1);
    proj_kernel<<<gproj, blk>>>(X, Wk, bk, gK, 1);
    proj_kernel<<<gproj, blk>>>(X, Wv, bv, gV, 1);

    dim3 gsc(S_LEN / 64, S_LEN / 64, BHN);    // (32, 32, 32)
    scores_kernel<<<gsc, blk>>>(gQ, gK, attn);

    dim3 gsm(S_LEN, BHN);                     // (2048, 32)
    softmax_kernel<<<gsm, blk>>>(attn);

    dim3 gav(S_LEN / 64, 1, BHN);             // (32, 1, 32)
    av_kernel<<<gav, blk>>>(attn, gV, gA);

    proj_kernel<<<gproj, blk>>>(gA, Wo, bo, out, 0);
}

// round 2
// speedup vs baseline: 1.8967x; 1.8967x over previous
#include <cuda_runtime.h>
#include <math.h>

#define S_LEN 2048
#define DM    1024
#define NH    16
#define HD    64
#define BATCH 2
#define BHN   (BATCH * NH)        // 32
#define MROWS (BATCH * S_LEN)     // 4096

// Scratch (alloc-free rule: __device__ globals).
__device__ float g_Q[(size_t)BHN * S_LEN * HD];
__device__ float g_K[(size_t)BHN * S_LEN * HD];
__device__ float g_V[(size_t)BHN * S_LEN * HD];
__device__ float g_A[(size_t)MROWS * DM];

// ---------------------------------------------------------------------------
// proj: C[r,e] = sum_d A[r,d]*W[e,d] + bias[e]   (M=4096, N=1024, K=1024)
// 128x128 tile, 256 threads, 8x8 micro-tile, k-chunk 16, LDG prefetch.
// reorder=1 -> write [B,H,S,Hd]; else row-major [M,N].
// ---------------------------------------------------------------------------
__global__ __launch_bounds__(256) void proj_kernel(
    const float* __restrict__ A, const float* __restrict__ W,
    const float* __restrict__ bias, float* __restrict__ out, int reorder)
{
    __shared__ float As[16][132];
    __shared__ float Bs[16][132];
    const int tid = threadIdx.x;
    const int tx = tid & 15, ty = tid >> 4;
    const int r0 = blockIdx.y * 128, c0 = blockIdx.x * 128;
    const int lg = tid & 3;          // col4 group within 16-wide chunk
    const int lr = tid >> 2;         // row 0..63

    float acc[8][8] = {};
    float4 pa0, pa1, pb0, pb1;

    // prefetch chunk 0
    pa0 = *(const float4*)&A[(size_t)(r0 + lr)      * DM + lg * 4];
    pa1 = *(const float4*)&A[(size_t)(r0 + lr + 64) * DM + lg * 4];
    pb0 = *(const float4*)&W[(size_t)(c0 + lr)      * DM + lg * 4];
    pb1 = *(const float4*)&W[(size_t)(c0 + lr + 64) * DM + lg * 4];

    for (int k0 = 0; k0 < DM; k0 += 16) {
        As[lg*4+0][lr]    = pa0.x; As[lg*4+1][lr]    = pa0.y;
        As[lg*4+2][lr]    = pa0.z; As[lg*4+3][lr]    = pa0.w;
        As[lg*4+0][lr+64] = pa1.x; As[lg*4+1][lr+64] = pa1.y;
        As[lg*4+2][lr+64] = pa1.z; As[lg*4+3][lr+64] = pa1.w;
        Bs[lg*4+0][lr]    = pb0.x; Bs[lg*4+1][lr]    = pb0.y;
        Bs[lg*4+2][lr]    = pb0.z; Bs[lg*4+3][lr]    = pb0.w;
        Bs[lg*4+0][lr+64] = pb1.x; Bs[lg*4+1][lr+64] = pb1.y;
        Bs[lg*4+2][lr+64] = pb1.z; Bs[lg*4+3][lr+64] = pb1.w;
        __syncthreads();

        if (k0 + 16 < DM) {
            int kn = k0 + 16;
            pa0 = *(const float4*)&A[(size_t)(r0 + lr)      * DM + kn + lg * 4];
            pa1 = *(const float4*)&A[(size_t)(r0 + lr + 64) * DM + kn + lg * 4];
            pb0 = *(const float4*)&W[(size_t)(c0 + lr)      * DM + kn + lg * 4];
            pb1 = *(const float4*)&W[(size_t)(c0 + lr + 64) * DM + kn + lg * 4];
        }

#pragma unroll
        for (int k = 0; k < 16; k++) {
            float4 av0 = *(const float4*)&As[k][ty * 8];
            float4 av1 = *(const float4*)&As[k][ty * 8 + 4];
            float4 bv0 = *(const float4*)&Bs[k][tx * 8];
            float4 bv1 = *(const float4*)&Bs[k][tx * 8 + 4];
            float a[8] = {av0.x, av0.y, av0.z, av0.w, av1.x, av1.y, av1.z, av1.w};
            float b[8] = {bv0.x, bv0.y, bv0.z, bv0.w, bv1.x, bv1.y, bv1.z, bv1.w};
#pragma unroll
            for (int i = 0; i < 8; i++)
#pragma unroll
                for (int j = 0; j < 8; j++)
                    acc[i][j] = fmaf(a[i], b[j], acc[i][j]);
        }
        __syncthreads();
    }

#pragma unroll
    for (int i = 0; i < 8; i++) {
        int r = r0 + ty * 8 + i;
        int bb = r >> 11, s = r & (S_LEN - 1);
#pragma unroll
        for (int jv = 0; jv < 2; jv++) {
            int e = c0 + tx * 8 + jv * 4;
            float4 v;
            v.x = acc[i][jv*4+0] + bias[e+0];
            v.y = acc[i][jv*4+1] + bias[e+1];
            v.z = acc[i][jv*4+2] + bias[e+2];
            v.w = acc[i][jv*4+3] + bias[e+3];
            if (reorder) {
                int h = e >> 6, hd = e & 63;
                *(float4*)&out[((size_t)(bb * NH + h) * S_LEN + s) * HD + hd] = v;
            } else {
                *(float4*)&out[(size_t)r * DM + e] = v;
            }
        }
    }
}

// ---------------------------------------------------------------------------
// scores: attn[bh,q,k] = 0.125 * dot(Q[bh,q,:], K[bh,k,:])   (K=64)
// 128x128 tile, same micro-structure; upper-tri tiles skipped (softmax will
// overwrite the full matrix anyway).
// ---------------------------------------------------------------------------
__global__ __launch_bounds__(256) void scores_kernel(
    const float* __restrict__ Q, const float* __restrict__ K,
    float* __restrict__ attn)
{
    const int kt = blockIdx.x, qt = blockIdx.y, bh = blockIdx.z;
    if (kt > qt) return;
    const float* Qb = Q + (size_t)bh * S_LEN * HD;
    const float* Kb = K + (size_t)bh * S_LEN * HD;
    float* Ab = attn + (size_t)bh * S_LEN * S_LEN;

    __shared__ float As[16][132];
    __shared__ float Bs[16][132];
    const int tid = threadIdx.x;
    const int tx = tid & 15, ty = tid >> 4;
    const int q0 = qt * 128, c0 = kt * 128;
    const int lg = tid & 3;
    const int lr = tid >> 2;

    float acc[8][8] = {};
    float4 pa0, pa1, pb0, pb1;
    pa0 = *(const float4*)&Qb[(size_t)(q0 + lr)      * HD + lg * 4];
    pa1 = *(const float4*)&Qb[(size_t)(q0 + lr + 64) * HD + lg * 4];
    pb0 = *(const float4*)&Kb[(size_t)(c0 + lr)      * HD + lg * 4];
    pb1 = *(const float4*)&Kb[(size_t)(c0 + lr + 64) * HD + lg * 4];

    for (int k0 = 0; k0 < HD; k0 += 16) {
        As[lg*4+0][lr]    = pa0.x; As[lg*4+1][lr]    = pa0.y;
        As[lg*4+2][lr]    = pa0.z; As[lg*4+3][lr]    = pa0.w;
        As[lg*4+0][lr+64] = pa1.x; As[lg*4+1][lr+64] = pa1.y;
        As[lg*4+2][lr+64] = pa1.z; As[lg*4+3][lr+64] = pa1.w;
        Bs[lg*4+0][lr]    = pb0.x; Bs[lg*4+1][lr]    = pb0.y;
        Bs[lg*4+2][lr]    = pb0.z; Bs[lg*4+3][lr]    = pb0.w;
        Bs[lg*4+0][lr+64] = pb1.x; Bs[lg*4+1][lr+64] = pb1.y;
        Bs[lg*4+2][lr+64] = pb1.z; Bs[lg*4+3][lr+64] = pb1.w;
        __syncthreads();

        if (k0 + 16 < HD) {
            int kn = k0 + 16;
            pa0 = *(const float4*)&Qb[(size_t)(q0 + lr)      * HD + kn + lg * 4];
            pa1 = *(const float4*)&Qb[(size_t)(q0 + lr + 64) * HD + kn + lg * 4];
            pb0 = *(const float4*)&Kb[(size_t)(c0 + lr)      * HD + kn + lg * 4];
            pb1 = *(const float4*)&Kb[(size_t)(c0 + lr + 64) * HD + kn + lg * 4];
        }

#pragma unroll
        for (int k = 0; k < 16; k++) {
            float4 av0 = *(const float4*)&As[k][ty * 8];
            float4 av1 = *(const float4*)&As[k][ty * 8 + 4];
            float4 bv0 = *(const float4*)&Bs[k][tx * 8];
            float4 bv1 = *(const float4*)&Bs[k][tx * 8 + 4];
            float a[8] = {av0.x, av0.y, av0.z, av0.w, av1.x, av1.y, av1.z, av1.w};
            float b[8] = {bv0.x, bv0.y, bv0.z, bv0.w, bv1.x, bv1.y, bv1.z, bv1.w};
#pragma unroll
            for (int i = 0; i < 8; i++)
#pragma unroll
                for (int j = 0; j < 8; j++)
                    acc[i][j] = fmaf(a[i], b[j], acc[i][j]);
        }
        __syncthreads();
    }

#pragma unroll
    for (int i = 0; i < 8; i++) {
        int q = q0 + ty * 8 + i;
#pragma unroll
        for (int jv = 0; jv < 2; jv++) {
            int c = c0 + tx * 8 + jv * 4;
            float4 v;
            v.x = acc[i][jv*4+0] * 0.125f;
            v.y = acc[i][jv*4+1] * 0.125f;
            v.z = acc[i][jv*4+2] * 0.125f;
            v.w = acc[i][jv*4+3] * 0.125f;
            *(float4*)&Ab[(size_t)q * S_LEN + c] = v;
        }
    }
}

// ---------------------------------------------------------------------------
// Row-wise causal softmax in place (vectorized). Writes zeros for k > q.
// ---------------------------------------------------------------------------
__global__ __launch_bounds__(256) void softmax_kernel(float* __restrict__ attn)
{
    const int q = blockIdx.x, bh = blockIdx.y;
    float* row = attn + ((size_t)bh * S_LEN + q) * S_LEN;
    const int tid = threadIdx.x;
    const int valid = q + 1;

    float4 v0 = *(const float4*)&row[4 * tid];
    float4 v1 = *(const float4*)&row[4 * (tid + 256)];
    float vals[8] = {v0.x, v0.y, v0.z, v0.w, v1.x, v1.y, v1.z, v1.w};
    const int b0 = 4 * tid, b1 = 4 * (tid + 256);

    float mx = -INFINITY;
#pragma unroll
    for (int i = 0; i < 8; i++) {
        int k = (i < 4) ? (b0 + i) : (b1 + i - 4);
        if (k >= valid) vals[i] = -INFINITY;
        mx = fmaxf(mx, vals[i]);
    }
#pragma unroll
    for (int o = 16; o; o >>= 1) mx = fmaxf(mx, __shfl_xor_sync(~0u, mx, o));
    __shared__ float sred[8];
    if ((tid & 31) == 0) sred[tid >> 5] = mx;
    __syncthreads();
    mx = sred[0];
#pragma unroll
    for (int i = 1; i < 8; i++) mx = fmaxf(mx, sred[i]);
    __syncthreads();

    float sum = 0.f;
#pragma unroll
    for (int i = 0; i < 8; i++) {
        float e = __expf(vals[i] - mx);   // exp(-inf)=0 handles masked lanes
        vals[i] = e;
        sum += e;
    }
#pragma unroll
    for (int o = 16; o; o >>= 1) sum += __shfl_xor_sync(~0u, sum, o);
    if ((tid & 31) == 0) sred[tid >> 5] = sum;
    __syncthreads();
    sum = 0.f;
#pragma unroll
    for (int i = 0; i < 8; i++) sum += sred[i];
    const float inv = 1.f / sum;

    float4 w0 = {vals[0]*inv, vals[1]*inv, vals[2]*inv, vals[3]*inv};
    float4 w1 = {vals[4]*inv, vals[5]*inv, vals[6]*inv, vals[7]*inv};
    *(float4*)&row[4 * tid]         = w0;
    *(float4*)&row[4 * (tid + 256)] = w1;
}

// ---------------------------------------------------------------------------
// av: A[bh,q,hd] = sum_k attn[bh,q,k]*V[bh,k,hd]  (causal bound), write [B,S,D]
// 128x64 tile, 256 threads, 8x4 micro-tile, k-chunk 32.
// ---------------------------------------------------------------------------
__global__ __launch_bounds__(256) void av_kernel(
    const float* __restrict__ attn, const float* __restrict__ V,
    float* __restrict__ Aout)
{
    const int qt = blockIdx.x, bh = blockIdx.z;
    const int q0 = qt * 128;
    const float* Pb = attn + (size_t)bh * S_LEN * S_LEN;
    const float* Vb = V + (size_t)bh * S_LEN * HD;

    __shared__ float Ps[32][132];
    __shared__ float Vs[32][64];
    const int tid = threadIdx.x;
    const int tx = tid & 15, ty = tid >> 4;
    const int pg = tid & 7;      // P col4 group 0..7
    const int pr = tid >> 3;     // P row 0..31
    const int kend = q0 + 128;   // probs are zero beyond q0+127 for this tile

    float acc[8][4] = {};
    for (int k0 = 0; k0 < kend; k0 += 32) {
#pragma unroll
        for (int m = 0; m < 4; m++) {
            float4 p = *(const float4*)&Pb[(size_t)(q0 + pr + 32*m) * S_LEN + k0 + pg*4];
            Ps[pg*4+0][pr + 32*m] = p.x; Ps[pg*4+1][pr + 32*m] = p.y;
            Ps[pg*4+2][pr + 32*m] = p.z; Ps[pg*4+3][pr + 32*m] = p.w;
        }
#pragma unroll
        for (int i = 0; i < 2; i++) {
            int idx = tid + i * 256;
            int vr = idx >> 4, vc = (idx & 15) * 4;
            *(float4*)&Vs[vr][vc] = *(const float4*)&Vb[(size_t)(k0 + vr) * HD + vc];
        }
        __syncthreads();

#pragma unroll
        for (int k = 0; k < 32; k++) {
            float4 av0 = *(const float4*)&Ps[k][ty * 8];
            float4 av1 = *(const float4*)&Ps[k][ty * 8 + 4];
            float4 bv  = *(const float4*)&Vs[k][tx * 4];
            float a[8] = {av0.x, av0.y, av0.z, av0.w, av1.x, av1.y, av1.z, av1.w};
            float b[4] = {bv.x, bv.y, bv.z, bv.w};
#pragma unroll
            for (int i = 0; i < 8; i++)
#pragma unroll
                for (int j = 0; j < 4; j++)
                    acc[i][j] = fmaf(a[i], b[j], acc[i][j]);
        }
        __syncthreads();
    }

    const int bb = bh / NH, h = bh % NH;
#pragma unroll
    for (int i = 0; i < 8; i++) {
        int s = q0 + ty * 8 + i;
        float4 v = {acc[i][0], acc[i][1], acc[i][2], acc[i][3]};
        *(float4*)&Aout[(size_t)(bb * S_LEN + s) * DM + h * HD + tx * 4] = v;
    }
}

// ---------------------------------------------------------------------------
extern "C" void kernel_launch(void* const* d_in, const int* in_sizes, int n_in,
                              void* d_out, int out_size)
{
    const float* X  = (const float*)d_in[0];
    const float* Wq = (const float*)d_in[1];
    const float* bq = (const float*)d_in[2];
    const float* Wk = (const float*)d_in[3];
    const float* bk = (const float*)d_in[4];
    const float* Wv = (const float*)d_in[5];
    const float* bv = (const float*)d_in[6];
    const float* Wo = (const float*)d_in[7];
    const float* bo = (const float*)d_in[8];

    float* out  = (float*)d_out;
    float* attn = out + (size_t)MROWS * DM;   // out [B,S,D] then attn [B,H,S,S]

    float *gQ, *gK, *gV, *gA;
    cudaGetSymbolAddress((void**)&gQ, g_Q);
    cudaGetSymbolAddress((void**)&gK, g_K);
    cudaGetSymbolAddress((void**)&gV, g_V);
    cudaGetSymbolAddress((void**)&gA, g_A);

    dim3 blk(256);
    dim3 gproj(DM / 128, MROWS / 128);        // (8, 32)
    proj_kernel<<<gproj, blk>>>(X, Wq, bq, gQ, 1);
    proj_kernel<<<gproj, blk>>>(X, Wk, bk, gK, 1);
    proj_kernel<<<gproj, blk>>>(X, Wv, bv, gV, 1);

    dim3 gsc(S_LEN / 128, S_LEN / 128, BHN);  // (16, 16, 32)
    scores_kernel<<<gsc, blk>>>(gQ, gK, attn);

    dim3 gsm(S_LEN, BHN);                     // (2048, 32)
    softmax_kernel<<<gsm, blk>>>(attn);

    dim3 gav(S_LEN / 128, 1, BHN);            // (16, 1, 32)
    av_kernel<<<gav, blk>>>(attn, gV, gA);

    proj_kernel<<<gproj, blk>>>(gA, Wo, bo, out, 0);
}

// round 4
// speedup vs baseline: 2.7830x; 1.4673x over previous
#include <cuda_runtime.h>
#include <cuda_bf16.h>
#include <math.h>
#include <stdint.h>

#define S_LEN 2048
#define DM    1024
#define NH    16
#define HD    64
#define BATCH 2
#define BHN   (BATCH * NH)        // 32
#define MROWS (BATCH * S_LEN)     // 4096
#define KCAT  3072                // 3 x DM (hi,hi,lo | hi,lo,hi)
#define NKCH  (KCAT / 64)         // 48 k-chunks of 64

// ---------------- scratch (__device__ globals; alloc-free rule) -------------
__device__ float g_Q[(size_t)BHN * S_LEN * HD];
__device__ float g_K[(size_t)BHN * S_LEN * HD];
__device__ float g_V[(size_t)BHN * S_LEN * HD];
__device__ float g_A[(size_t)MROWS * DM];
__device__ __nv_bfloat16 g_Xcat[(size_t)MROWS * KCAT];
__device__ __nv_bfloat16 g_Acat[(size_t)MROWS * KCAT];
__device__ __nv_bfloat16 g_Wqc[(size_t)DM * KCAT];
__device__ __nv_bfloat16 g_Wkc[(size_t)DM * KCAT];
__device__ __nv_bfloat16 g_Wvc[(size_t)DM * KCAT];
__device__ __nv_bfloat16 g_Woc[(size_t)DM * KCAT];

// ---------------- helpers ---------------------------------------------------
__device__ __forceinline__ uint32_t smem_u32(const void* p) {
    uint32_t a;
    asm("{ .reg .u64 t; cvta.to.shared.u64 t, %1; cvt.u32.u64 %0, t; }"
        : "=r"(a) : "l"(p));
    return a;
}
#define SW128(o) ((o) ^ (((o) >> 3) & 0x70))

__device__ __forceinline__ void ldm_x4(uint32_t* r, uint32_t addr) {
    asm volatile("ldmatrix.sync.aligned.m8n8.x4.shared.b16 {%0,%1,%2,%3}, [%4];"
                 : "=r"(r[0]), "=r"(r[1]), "=r"(r[2]), "=r"(r[3]) : "r"(addr));
}
__device__ __forceinline__ void mma_bf16(float* c, const uint32_t* a,
                                         uint32_t b0, uint32_t b1) {
    asm volatile(
        "mma.sync.aligned.m16n8k16.row.col.f32.bf16.bf16.f32 "
        "{%0,%1,%2,%3}, {%4,%5,%6,%7}, {%8,%9}, {%0,%1,%2,%3};"
        : "+f"(c[0]), "+f"(c[1]), "+f"(c[2]), "+f"(c[3])
        : "r"(a[0]), "r"(a[1]), "r"(a[2]), "r"(a[3]), "r"(b0), "r"(b1));
}

// ---------------------------------------------------------------------------
// fp32 -> bf16 split-concat.  mode 0 (A): [hi,hi,lo]   mode 1 (B): [hi,lo,hi]
// ---------------------------------------------------------------------------
__global__ __launch_bounds__(256) void convert_cat(
    const float* __restrict__ src, __nv_bfloat16* __restrict__ dst,
    int rows, int mode)
{
    int n = rows * (DM / 4);
    for (int i = blockIdx.x * blockDim.x + threadIdx.x; i < n;
         i += gridDim.x * blockDim.x) {
        int r = i / (DM / 4), cq = i - r * (DM / 4);
        float4 v = *(const float4*)&src[(size_t)r * DM + cq * 4];
        float f[4] = {v.x, v.y, v.z, v.w};
        __nv_bfloat16 hi[4], lo[4];
#pragma unroll
        for (int j = 0; j < 4; j++) {
            hi[j] = __float2bfloat16(f[j]);
            lo[j] = __float2bfloat16(f[j] - __bfloat162float(hi[j]));
        }
        __nv_bfloat162 h01 = __halves2bfloat162(hi[0], hi[1]);
        __nv_bfloat162 h23 = __halves2bfloat162(hi[2], hi[3]);
        __nv_bfloat162 l01 = __halves2bfloat162(lo[0], lo[1]);
        __nv_bfloat162 l23 = __halves2bfloat162(lo[2], lo[3]);
        size_t base = (size_t)r * KCAT + cq * 4;
        __nv_bfloat162* d0 = (__nv_bfloat162*)&dst[base];
        __nv_bfloat162* d1 = (__nv_bfloat162*)&dst[base + DM];
        __nv_bfloat162* d2 = (__nv_bfloat162*)&dst[base + 2 * DM];
        d0[0] = h01; d0[1] = h23;
        if (mode == 0) { d1[0] = h01; d1[1] = h23; d2[0] = l01; d2[1] = l23; }
        else           { d1[0] = l01; d1[1] = l23; d2[0] = h01; d2[1] = h23; }
    }
}

// ---------------------------------------------------------------------------
// mma.sync bf16 GEMM: out[r,c] = sum_k A[r,k]*B[c,k] + bias[c]
// A [4096,KCAT], B [1024,KCAT] bf16.  128x128 tile, 8 warps (2m x 4n),
// warp tile 64x32, k-chunk 64, cp.async double buffer, SW128 smem.
// reorder=1 -> [B,H,S,Hd]; else row-major.
// ---------------------------------------------------------------------------
#define GEMM_SMEM 65536   // A:2x16K, B:2x16K

__global__ __launch_bounds__(256) void gemm_mma(
    const __nv_bfloat16* __restrict__ A, const __nv_bfloat16* __restrict__ B,
    const float* __restrict__ bias, float* __restrict__ out, int reorder)
{
    extern __shared__ __align__(1024) char smem[];
    const int tid = threadIdx.x;
    const int wid = tid >> 5, lane = tid & 31;
    const int warp_m = wid >> 2;          // 0..1  (64 rows)
    const int warp_n = wid & 3;           // 0..3  (32 cols)
    const uint32_t sb = smem_u32(smem);

    const int r0 = blockIdx.y * 128, c0 = blockIdx.x * 128;

    const int ls = tid & 7;     // 16B segment 0..7
    const int lr = tid >> 3;    // row 0..31

    // stage offsets: A st 0/1 at 0/16K; B st 0/1 at 32K/48K
#define LOAD_STAGE(chunk, stage) do {                                          \
        uint32_t ab = sb + (stage) * 16384;                                    \
        uint32_t bb = sb + 32768 + (stage) * 16384;                            \
        size_t kb = (size_t)(chunk) * 64 + ls * 8;                             \
        _Pragma("unroll")                                                      \
        for (int i_ = 0; i_ < 4; i_++) {                                       \
            int r_ = lr + 32 * i_;                                             \
            uint32_t off = SW128(r_ * 128 + ls * 16);                          \
            const __nv_bfloat16* ga = &A[(size_t)(r0 + r_) * KCAT + kb];       \
            const __nv_bfloat16* gb = &B[(size_t)(c0 + r_) * KCAT + kb];       \
            asm volatile("cp.async.cg.shared.global [%0], [%1], 16;"           \
                         :: "r"(ab + off), "l"(ga));                           \
            asm volatile("cp.async.cg.shared.global [%0], [%1], 16;"           \
                         :: "r"(bb + off), "l"(gb));                           \
        }                                                                      \
        asm volatile("cp.async.commit_group;");                                \
    } while (0)

    float acc[4][4][4] = {};   // [mt][nt][c0..c3]

    LOAD_STAGE(0, 0);

    for (int c = 0; c < NKCH; c++) {
        const int st = c & 1;
        if (c + 1 < NKCH) {
            LOAD_STAGE(c + 1, st ^ 1);
            asm volatile("cp.async.wait_group 1;");
        } else {
            asm volatile("cp.async.wait_group 0;");
        }
        __syncthreads();

        const uint32_t abase = sb + st * 16384;
        const uint32_t bbase = sb + 32768 + st * 16384;
#pragma unroll
        for (int ks = 0; ks < 4; ks++) {
            uint32_t af[4][4];
#pragma unroll
            for (int mt = 0; mt < 4; mt++) {
                int row = warp_m * 64 + mt * 16 + (lane & 15);
                int seg = ks * 2 + (lane >> 4);
                ldm_x4(af[mt], abase + SW128(row * 128 + seg * 16));
            }
            uint32_t bf[2][4];
#pragma unroll
            for (int h = 0; h < 2; h++) {
                int row = warp_n * 32 + h * 16 + ((lane >> 4) & 1) * 8 + (lane & 7);
                int seg = ks * 2 + ((lane >> 3) & 1);
                ldm_x4(bf[h], bbase + SW128(row * 128 + seg * 16));
            }
#pragma unroll
            for (int mt = 0; mt < 4; mt++)
#pragma unroll
                for (int nt = 0; nt < 4; nt++)
                    mma_bf16(acc[mt][nt], af[mt],
                             bf[nt >> 1][(nt & 1) * 2], bf[nt >> 1][(nt & 1) * 2 + 1]);
        }
        __syncthreads();
    }

    // epilogue: c0=(m=lane/4, n=2(lane%3..)), c1=n+1, c2=m+8, c3=m+8,n+1
    const int mrow = lane >> 2;
    const int ncol = 2 * (lane & 3);
#pragma unroll
    for (int mt = 0; mt < 4; mt++) {
#pragma unroll
        for (int nt = 0; nt < 4; nt++) {
            int cg = c0 + warp_n * 32 + nt * 8 + ncol;
            float b0 = __ldg(&bias[cg]), b1 = __ldg(&bias[cg + 1]);
#pragma unroll
            for (int half = 0; half < 2; half++) {
                int r = r0 + warp_m * 64 + mt * 16 + mrow + half * 8;
                float2 v = {acc[mt][nt][half * 2] + b0,
                            acc[mt][nt][half * 2 + 1] + b1};
                if (reorder) {
                    int bb = r >> 11, s = r & (S_LEN - 1);
                    int h = cg >> 6, hd = cg & 63;
                    *(float2*)&out[((size_t)(bb * NH + h) * S_LEN + s) * HD + hd] = v;
                } else {
                    *(float2*)&out[(size_t)r * DM + cg] = v;
                }
            }
        }
    }
}

// ---------------------------------------------------------------------------
// scores: attn[bh,q,k] = 0.125 * dot(Q,K)   (fp32 SIMT)
// ---------------------------------------------------------------------------
__global__ __launch_bounds__(256) void scores_kernel(
    const float* __restrict__ Q, const float* __restrict__ K,
    float* __restrict__ attn)
{
    const int kt = blockIdx.x, qt = blockIdx.y, bh = blockIdx.z;
    if (kt > qt) return;
    const float* Qb = Q + (size_t)bh * S_LEN * HD;
    const float* Kb = K + (size_t)bh * S_LEN * HD;
    float* Ab = attn + (size_t)bh * S_LEN * S_LEN;

    __shared__ float As[16][132];
    __shared__ float Bs[16][132];
    const int tid = threadIdx.x;
    const int tx = tid & 15, ty = tid >> 4;
    const int q0 = qt * 128, c0 = kt * 128;
    const int lg = tid & 3;
    const int lr = tid >> 2;

    float acc[8][8] = {};
    float4 pa0, pa1, pb0, pb1;
    pa0 = *(const float4*)&Qb[(size_t)(q0 + lr)      * HD + lg * 4];
    pa1 = *(const float4*)&Qb[(size_t)(q0 + lr + 64) * HD + lg * 4];
    pb0 = *(const float4*)&Kb[(size_t)(c0 + lr)      * HD + lg * 4];
    pb1 = *(const float4*)&Kb[(size_t)(c0 + lr + 64) * HD + lg * 4];

    for (int k0 = 0; k0 < HD; k0 += 16) {
        As[lg*4+0][lr]    = pa0.x; As[lg*4+1][lr]    = pa0.y;
        As[lg*4+2][lr]    = pa0.z; As[lg*4+3][lr]    = pa0.w;
        As[lg*4+0][lr+64] = pa1.x; As[lg*4+1][lr+64] = pa1.y;
        As[lg*4+2][lr+64] = pa1.z; As[lg*4+3][lr+64] = pa1.w;
        Bs[lg*4+0][lr]    = pb0.x; Bs[lg*4+1][lr]    = pb0.y;
        Bs[lg*4+2][lr]    = pb0.z; Bs[lg*4+3][lr]    = pb0.w;
        Bs[lg*4+0][lr+64] = pb1.x; Bs[lg*4+1][lr+64] = pb1.y;
        Bs[lg*4+2][lr+64] = pb1.z; Bs[lg*4+3][lr+64] = pb1.w;
        __syncthreads();

        if (k0 + 16 < HD) {
            int kn = k0 + 16;
            pa0 = *(const float4*)&Qb[(size_t)(q0 + lr)      * HD + kn + lg * 4];
            pa1 = *(const float4*)&Qb[(size_t)(q0 + lr + 64) * HD + kn + lg * 4];
            pb0 = *(const float4*)&Kb[(size_t)(c0 + lr)      * HD + kn + lg * 4];
            pb1 = *(const float4*)&Kb[(size_t)(c0 + lr + 64) * HD + kn + lg * 4];
        }

#pragma unroll
        for (int k = 0; k < 16; k++) {
            float4 av0 = *(const float4*)&As[k][ty * 8];
            float4 av1 = *(const float4*)&As[k][ty * 8 + 4];
            float4 bv0 = *(const float4*)&Bs[k][tx * 8];
            float4 bv1 = *(const float4*)&Bs[k][tx * 8 + 4];
            float a[8] = {av0.x, av0.y, av0.z, av0.w, av1.x, av1.y, av1.z, av1.w};
            float b[8] = {bv0.x, bv0.y, bv0.z, bv0.w, bv1.x, bv1.y, bv1.z, bv1.w};
#pragma unroll
            for (int i = 0; i < 8; i++)
#pragma unroll
                for (int j = 0; j < 8; j++)
                    acc[i][j] = fmaf(a[i], b[j], acc[i][j]);
        }
        __syncthreads();
    }

#pragma unroll
    for (int i = 0; i < 8; i++) {
        int q = q0 + ty * 8 + i;
#pragma unroll
        for (int jv = 0; jv < 2; jv++) {
            int c = c0 + tx * 8 + jv * 4;
            float4 v;
            v.x = acc[i][jv*4+0] * 0.125f;
            v.y = acc[i][jv*4+1] * 0.125f;
            v.z = acc[i][jv*4+2] * 0.125f;
            v.w = acc[i][jv*4+3] * 0.125f;
            *(float4*)&Ab[(size_t)q * S_LEN + c] = v;
        }
    }
}

// ---------------------------------------------------------------------------
// Row-wise causal softmax in place; skips loads of fully-masked segments.
// ---------------------------------------------------------------------------
__global__ __launch_bounds__(256) void softmax_kernel(float* __restrict__ attn)
{
    const int q = blockIdx.x, bh = blockIdx.y;
    float* row = attn + ((size_t)bh * S_LEN + q) * S_LEN;
    const int tid = threadIdx.x;
    const int valid = q + 1;
    const int b0 = 4 * tid, b1 = 4 * (tid + 256);

    float4 v0 = {-INFINITY, -INFINITY, -INFINITY, -INFINITY}, v1 = v0;
    if (b0 < valid) v0 = *(const float4*)&row[b0];
    if (b1 < valid) v1 = *(const float4*)&row[b1];
    float vals[8] = {v0.x, v0.y, v0.z, v0.w, v1.x, v1.y, v1.z, v1.w};

    float mx = -INFINITY;
#pragma unroll
    for (int i = 0; i < 8; i++) {
        int k = (i < 4) ? (b0 + i) : (b1 + i - 4);
        if (k >= valid) vals[i] = -INFINITY;
        mx = fmaxf(mx, vals[i]);
    }
#pragma unroll
    for (int o = 16; o; o >>= 1) mx = fmaxf(mx, __shfl_xor_sync(~0u, mx, o));
    __shared__ float sred[8];
    if ((tid & 31) == 0) sred[tid >> 5] = mx;
    __syncthreads();
    mx = sred[0];
#pragma unroll
    for (int i = 1; i < 8; i++) mx = fmaxf(mx, sred[i]);
    __syncthreads();

    float sum = 0.f;
#pragma unroll
    for (int i = 0; i < 8; i++) {
        float e = __expf(vals[i] - mx);
        vals[i] = e;
        sum += e;
    }
#pragma unroll
    for (int o = 16; o; o >>= 1) sum += __shfl_xor_sync(~0u, sum, o);
    if ((tid & 31) == 0) sred[tid >> 5] = sum;
    __syncthreads();
    sum = 0.f;
#pragma unroll
    for (int i = 0; i < 8; i++) sum += sred[i];
    const float inv = 1.f / sum;

    float4 w0 = {vals[0]*inv, vals[1]*inv, vals[2]*inv, vals[3]*inv};
    float4 w1 = {vals[4]*inv, vals[5]*inv, vals[6]*inv, vals[7]*inv};
    *(float4*)&row[b0] = w0;
    *(float4*)&row[b1] = w1;
}

// ---------------------------------------------------------------------------
// av: A[bh,q,hd] = sum_k attn[bh,q,k]*V[bh,k,hd]  (causal bound), write [B,S,D]
// ---------------------------------------------------------------------------
__global__ __launch_bounds__(256) void av_kernel(
    const float* __restrict__ attn, const float* __restrict__ V,
    float* __restrict__ Aout)
{
    const int qt = blockIdx.x, bh = blockIdx.z;
    const int q0 = qt * 128;
    const float* Pb = attn + (size_t)bh * S_LEN * S_LEN;
    const float* Vb = V + (size_t)bh * S_LEN * HD;

    __shared__ float Ps[32][132];
    __shared__ float Vs[32][64];
    const int tid = threadIdx.x;
    const int tx = tid & 15, ty = tid >> 4;
    const int pg = tid & 7;
    const int pr = tid >> 3;
    const int kend = q0 + 128;

    float acc[8][4] = {};
    for (int k0 = 0; k0 < kend; k0 += 32) {
#pragma unroll
        for (int m = 0; m < 4; m++) {
            float4 p = *(const float4*)&Pb[(size_t)(q0 + pr + 32*m) * S_LEN + k0 + pg*4];
            Ps[pg*4+0][pr + 32*m] = p.x; Ps[pg*4+1][pr + 32*m] = p.y;
            Ps[pg*4+2][pr + 32*m] = p.z; Ps[pg*4+3][pr + 32*m] = p.w;
        }
#pragma unroll
        for (int i = 0; i < 2; i++) {
            int idx = tid + i * 256;
            int vr = idx >> 4, vc = (idx & 15) * 4;
            *(float4*)&Vs[vr][vc] = *(const float4*)&Vb[(size_t)(k0 + vr) * HD + vc];
        }
        __syncthreads();

#pragma unroll
        for (int k = 0; k < 32; k++) {
            float4 av0 = *(const float4*)&Ps[k][ty * 8];
            float4 av1 = *(const float4*)&Ps[k][ty * 8 + 4];
            float4 bv  = *(const float4*)&Vs[k][tx * 4];
            float a[8] = {av0.x, av0.y, av0.z, av0.w, av1.x, av1.y, av1.z, av1.w};
            float b[4] = {bv.x, bv.y, bv.z, bv.w};
#pragma unroll
            for (int i = 0; i < 8; i++)
#pragma unroll
                for (int j = 0; j < 4; j++)
                    acc[i][j] = fmaf(a[i], b[j], acc[i][j]);
        }
        __syncthreads();
    }

    const int bb = bh / NH, h = bh % NH;
#pragma unroll
    for (int i = 0; i < 8; i++) {
        int s = q0 + ty * 8 + i;
        float4 v = {acc[i][0], acc[i][1], acc[i][2], acc[i][3]};
        *(float4*)&Aout[(size_t)(bb * S_LEN + s) * DM + h * HD + tx * 4] = v;
    }
}

// ---------------------------------------------------------------------------
extern "C" void kernel_launch(void* const* d_in, const int* in_sizes, int n_in,
                              void* d_out, int out_size)
{
    const float* X  = (const float*)d_in[0];
    const float* Wq = (const float*)d_in[1];
    const float* bq = (const float*)d_in[2];
    const float* Wk = (const float*)d_in[3];
    const float* bk = (const float*)d_in[4];
    const float* Wv = (const float*)d_in[5];
    const float* bv = (const float*)d_in[6];
    const float* Wo = (const float*)d_in[7];
    const float* bo = (const float*)d_in[8];

    float* out  = (float*)d_out;
    float* attn = out + (size_t)MROWS * DM;   // out [B,S,D] then attn [B,H,S,S]

    float *gQ, *gK, *gV, *gA;
    __nv_bfloat16 *gXc, *gAc, *gWq, *gWk, *gWv, *gWo;
    cudaGetSymbolAddress((void**)&gQ, g_Q);
    cudaGetSymbolAddress((void**)&gK, g_K);
    cudaGetSymbolAddress((void**)&gV, g_V);
    cudaGetSymbolAddress((void**)&gA, g_A);
    cudaGetSymbolAddress((void**)&gXc, g_Xcat);
    cudaGetSymbolAddress((void**)&gAc, g_Acat);
    cudaGetSymbolAddress((void**)&gWq, g_Wqc);
    cudaGetSymbolAddress((void**)&gWk, g_Wkc);
    cudaGetSymbolAddress((void**)&gWv, g_Wvc);
    cudaGetSymbolAddress((void**)&gWo, g_Woc);

    static int smem_set = 0;
    if (!smem_set) {
        cudaFuncSetAttribute(gemm_mma, cudaFuncAttributeMaxDynamicSharedMemorySize,
                             GEMM_SMEM);
        smem_set = 1;
    }

    dim3 blk(256);

    // bf16 split-concat conversions
    convert_cat<<<512, blk>>>(Wq, gWq, DM, 1);
    convert_cat<<<512, blk>>>(Wk, gWk, DM, 1);
    convert_cat<<<512, blk>>>(Wv, gWv, DM, 1);
    convert_cat<<<512, blk>>>(Wo, gWo, DM, 1);
    convert_cat<<<1024, blk>>>(X, gXc, MROWS, 0);

    // projections on tensor cores (mma.sync bf16, split-K exact)
    dim3 ggemm(DM / 128, MROWS / 128);        // (8, 32)
    gemm_mma<<<ggemm, blk, GEMM_SMEM>>>(gXc, gWq, bq, gQ, 1);
    gemm_mma<<<ggemm, blk, GEMM_SMEM>>>(gXc, gWk, bk, gK, 1);
    gemm_mma<<<ggemm, blk, GEMM_SMEM>>>(gXc, gWv, bv, gV, 1);

    dim3 gsc(S_LEN / 128, S_LEN / 128, BHN);  // (16, 16, 32)
    scores_kernel<<<gsc, blk>>>(gQ, gK, attn);

    dim3 gsm(S_LEN, BHN);                     // (2048, 32)
    softmax_kernel<<<gsm, blk>>>(attn);

    dim3 gav(S_LEN / 128, 1, BHN);            // (16, 1, 32)
    av_kernel<<<gav, blk>>>(attn, gV, gA);

    convert_cat<<<1024, blk>>>(gA, gAc, MROWS, 0);
    gemm_mma<<<ggemm, blk, GEMM_SMEM>>>(gAc, gWo, bo, out, 0);
}

// round 5
// speedup vs baseline: 3.9902x; 1.4338x over previous
#include <cuda_runtime.h>
#include <cuda_bf16.h>
#include <math.h>
#include <stdint.h>

#define S_LEN 2048
#define DM    1024
#define NH    16
#define HD    64
#define BATCH 2
#define BHN   (BATCH * NH)        // 32
#define MROWS (BATCH * S_LEN)     // 4096
#define KCAT  3072                // 3 x DM (hi,hi,lo | hi,lo,hi)
#define NKCH  (KCAT / 64)         // 48
#define KQK   192                 // 3 x HD

// ---------------- scratch (__device__ globals) ------------------------------
__device__ __nv_bfloat16 g_Xcat[(size_t)MROWS * KCAT];
__device__ __nv_bfloat16 g_Acat[(size_t)MROWS * KCAT];
__device__ __nv_bfloat16 g_Wqc[(size_t)DM * KCAT];
__device__ __nv_bfloat16 g_Wkc[(size_t)DM * KCAT];
__device__ __nv_bfloat16 g_Wvc[(size_t)DM * KCAT];
__device__ __nv_bfloat16 g_Woc[(size_t)DM * KCAT];
__device__ __nv_bfloat16 g_Qc[(size_t)BHN * S_LEN * KQK];   // [hi,hi,lo]
__device__ __nv_bfloat16 g_Kc[(size_t)BHN * S_LEN * KQK];   // [hi,lo,hi]
__device__ __nv_bfloat16 g_Vth[(size_t)BHN * HD * S_LEN];   // V^T hi
__device__ __nv_bfloat16 g_Vtl[(size_t)BHN * HD * S_LEN];   // V^T lo
__device__ __nv_bfloat16 g_Ph[(size_t)BHN * S_LEN * S_LEN]; // P hi
__device__ __nv_bfloat16 g_Pl[(size_t)BHN * S_LEN * S_LEN]; // P lo

// ---------------- helpers ---------------------------------------------------
__device__ __forceinline__ uint32_t smem_u32(const void* p) {
    uint32_t a;
    asm("{ .reg .u64 t; cvta.to.shared.u64 t, %1; cvt.u32.u64 %0, t; }"
        : "=r"(a) : "l"(p));
    return a;
}
#define SW128(o) ((o) ^ (((o) >> 3) & 0x70))

__device__ __forceinline__ void ldm_x4(uint32_t* r, uint32_t addr) {
    asm volatile("ldmatrix.sync.aligned.m8n8.x4.shared.b16 {%0,%1,%2,%3}, [%4];"
                 : "=r"(r[0]), "=r"(r[1]), "=r"(r[2]), "=r"(r[3]) : "r"(addr));
}
__device__ __forceinline__ void mma_bf16(float* c, const uint32_t* a,
                                         uint32_t b0, uint32_t b1) {
    asm volatile(
        "mma.sync.aligned.m16n8k16.row.col.f32.bf16.bf16.f32 "
        "{%0,%1,%2,%3}, {%4,%5,%6,%7}, {%8,%9}, {%0,%1,%2,%3};"
        : "+f"(c[0]), "+f"(c[1]), "+f"(c[2]), "+f"(c[3])
        : "r"(a[0]), "r"(a[1]), "r"(a[2]), "r"(a[3]), "r"(b0), "r"(b1));
}
#define CP16(dst, src) \
    asm volatile("cp.async.cg.shared.global [%0], [%1], 16;" :: "r"(dst), "l"(src))
#define CP_COMMIT() asm volatile("cp.async.commit_group;")

// ---------------------------------------------------------------------------
// fp32 -> bf16 split-concat.  mode 0 (A): [hi,hi,lo]   mode 1 (B): [hi,lo,hi]
// ---------------------------------------------------------------------------
__global__ __launch_bounds__(256) void convert_cat(
    const float* __restrict__ src, __nv_bfloat16* __restrict__ dst,
    int rows, int mode)
{
    int n = rows * (DM / 4);
    for (int i = blockIdx.x * blockDim.x + threadIdx.x; i < n;
         i += gridDim.x * blockDim.x) {
        int r = i / (DM / 4), cq = i - r * (DM / 4);
        float4 v = *(const float4*)&src[(size_t)r * DM + cq * 4];
        float f[4] = {v.x, v.y, v.z, v.w};
        __nv_bfloat16 hi[4], lo[4];
#pragma unroll
        for (int j = 0; j < 4; j++) {
            hi[j] = __float2bfloat16(f[j]);
            lo[j] = __float2bfloat16(f[j] - __bfloat162float(hi[j]));
        }
        __nv_bfloat162 h01 = __halves2bfloat162(hi[0], hi[1]);
        __nv_bfloat162 h23 = __halves2bfloat162(hi[2], hi[3]);
        __nv_bfloat162 l01 = __halves2bfloat162(lo[0], lo[1]);
        __nv_bfloat162 l23 = __halves2bfloat162(lo[2], lo[3]);
        size_t base = (size_t)r * KCAT + cq * 4;
        __nv_bfloat162* d0 = (__nv_bfloat162*)&dst[base];
        __nv_bfloat162* d1 = (__nv_bfloat162*)&dst[base + DM];
        __nv_bfloat162* d2 = (__nv_bfloat162*)&dst[base + 2 * DM];
        d0[0] = h01; d0[1] = h23;
        if (mode == 0) { d1[0] = h01; d1[1] = h23; d2[0] = l01; d2[1] = l23; }
        else           { d1[0] = l01; d1[1] = l23; d2[0] = h01; d2[1] = h23; }
    }
}

// ---------------------------------------------------------------------------
// mma.sync bf16 GEMM: C[r,c] = sum_k A[r,k]*B[c,k] + bias[c]
// omode 0: fp32 row-major out.   1: Q split A-layout.  2: K split B-layout.
// omode 3: V transposed hi/lo planes.
// ---------------------------------------------------------------------------
#define GEMM_SMEM 65536

__global__ __launch_bounds__(256) void gemm_mma(
    const __nv_bfloat16* __restrict__ A, const __nv_bfloat16* __restrict__ B,
    const float* __restrict__ bias, float* __restrict__ outf,
    __nv_bfloat16* __restrict__ ob1, __nv_bfloat16* __restrict__ ob2, int omode)
{
    extern __shared__ __align__(1024) char smem[];
    const int tid = threadIdx.x;
    const int wid = tid >> 5, lane = tid & 31;
    const int warp_m = wid >> 2;
    const int warp_n = wid & 3;
    const uint32_t sb = smem_u32(smem);

    const int r0 = blockIdx.y * 128, c0 = blockIdx.x * 128;
    const int ls = tid & 7;
    const int lr = tid >> 3;

#define LOAD_STAGE(chunk, stage) do {                                          \
        uint32_t ab = sb + (stage) * 16384;                                    \
        uint32_t bb = sb + 32768 + (stage) * 16384;                            \
        size_t kb = (size_t)(chunk) * 64 + ls * 8;                             \
        _Pragma("unroll")                                                      \
        for (int i_ = 0; i_ < 4; i_++) {                                       \
            int r_ = lr + 32 * i_;                                             \
            uint32_t off = SW128(r_ * 128 + ls * 16);                          \
            CP16(ab + off, &A[(size_t)(r0 + r_) * KCAT + kb]);                 \
            CP16(bb + off, &B[(size_t)(c0 + r_) * KCAT + kb]);                 \
        }                                                                      \
        CP_COMMIT();                                                           \
    } while (0)

    float acc[4][4][4] = {};
    LOAD_STAGE(0, 0);

    for (int c = 0; c < NKCH; c++) {
        const int st = c & 1;
        if (c + 1 < NKCH) {
            LOAD_STAGE(c + 1, st ^ 1);
            asm volatile("cp.async.wait_group 1;");
        } else {
            asm volatile("cp.async.wait_group 0;");
        }
        __syncthreads();

        const uint32_t abase = sb + st * 16384;
        const uint32_t bbase = sb + 32768 + st * 16384;
#pragma unroll
        for (int ks = 0; ks < 4; ks++) {
            uint32_t af[4][4];
#pragma unroll
            for (int mt = 0; mt < 4; mt++) {
                int row = warp_m * 64 + mt * 16 + (lane & 15);
                int seg = ks * 2 + (lane >> 4);
                ldm_x4(af[mt], abase + SW128(row * 128 + seg * 16));
            }
            uint32_t bf[2][4];
#pragma unroll
            for (int h = 0; h < 2; h++) {
                int row = warp_n * 32 + h * 16 + ((lane >> 4) & 1) * 8 + (lane & 7);
                int seg = ks * 2 + ((lane >> 3) & 1);
                ldm_x4(bf[h], bbase + SW128(row * 128 + seg * 16));
            }
#pragma unroll
            for (int mt = 0; mt < 4; mt++)
#pragma unroll
                for (int nt = 0; nt < 4; nt++)
                    mma_bf16(acc[mt][nt], af[mt],
                             bf[nt >> 1][(nt & 1) * 2], bf[nt >> 1][(nt & 1) * 2 + 1]);
        }
        __syncthreads();
    }
#undef LOAD_STAGE

    const int mrow = lane >> 2;
    const int ncol = 2 * (lane & 3);
#pragma unroll
    for (int mt = 0; mt < 4; mt++) {
#pragma unroll
        for (int nt = 0; nt < 4; nt++) {
            int cg = c0 + warp_n * 32 + nt * 8 + ncol;
            float b0 = __ldg(&bias[cg]), b1 = __ldg(&bias[cg + 1]);
#pragma unroll
            for (int half = 0; half < 2; half++) {
                int r = r0 + warp_m * 64 + mt * 16 + mrow + half * 8;
                float v0 = acc[mt][nt][half * 2] + b0;
                float v1 = acc[mt][nt][half * 2 + 1] + b1;
                if (omode == 0) {
                    float2 v = {v0, v1};
                    *(float2*)&outf[(size_t)r * DM + cg] = v;
                } else {
                    int bb = r >> 11, s = r & (S_LEN - 1);
                    int h = cg >> 6, hd = cg & 63;
                    __nv_bfloat16 h0 = __float2bfloat16(v0);
                    __nv_bfloat16 h1 = __float2bfloat16(v1);
                    __nv_bfloat16 l0 = __float2bfloat16(v0 - __bfloat162float(h0));
                    __nv_bfloat16 l1 = __float2bfloat16(v1 - __bfloat162float(h1));
                    __nv_bfloat162 hh = __halves2bfloat162(h0, h1);
                    __nv_bfloat162 ll = __halves2bfloat162(l0, l1);
                    if (omode == 3) {
                        size_t pb = ((size_t)(bb * NH + h) * HD + hd) * S_LEN + s;
                        ob1[pb] = h0; ob1[pb + S_LEN] = h1;
                        ob2[pb] = l0; ob2[pb + S_LEN] = l1;
                    } else {
                        size_t base = ((size_t)(bb * NH + h) * S_LEN + s) * KQK + hd;
                        *(__nv_bfloat162*)&ob1[base] = hh;
                        if (omode == 1) {
                            *(__nv_bfloat162*)&ob1[base + HD] = hh;
                            *(__nv_bfloat162*)&ob1[base + 2 * HD] = ll;
                        } else {
                            *(__nv_bfloat162*)&ob1[base + HD] = ll;
                            *(__nv_bfloat162*)&ob1[base + 2 * HD] = hh;
                        }
                    }
                }
            }
        }
    }
}

// ---------------------------------------------------------------------------
// scores_mma: attn[bh,q,k] = 0.125 * sum Q*K  via bf16 split (K'=192)
// 128x128 tile per CTA; skip kt > qt.
// ---------------------------------------------------------------------------
#define SC_SMEM 65536

__global__ __launch_bounds__(256) void scores_mma(
    const __nv_bfloat16* __restrict__ Qc, const __nv_bfloat16* __restrict__ Kc,
    float* __restrict__ attn)
{
    const int kt = blockIdx.x, qt = blockIdx.y, bh = blockIdx.z;
    if (kt > qt) return;
    extern __shared__ __align__(1024) char smem[];
    const int tid = threadIdx.x;
    const int wid = tid >> 5, lane = tid & 31;
    const int warp_m = wid >> 2;
    const int warp_n = wid & 3;
    const uint32_t sb = smem_u32(smem);
    const int q0 = qt * 128, c0 = kt * 128;

    const __nv_bfloat16* Ab = Qc + (size_t)bh * S_LEN * KQK;
    const __nv_bfloat16* Bb = Kc + (size_t)bh * S_LEN * KQK;
    const int ls = tid & 7;
    const int lr = tid >> 3;

#define SC_LOAD(chunk, stage) do {                                             \
        uint32_t ab = sb + (stage) * 16384;                                    \
        uint32_t bb = sb + 32768 + (stage) * 16384;                            \
        size_t kb = (size_t)(chunk) * 64 + ls * 8;                             \
        _Pragma("unroll")                                                      \
        for (int i_ = 0; i_ < 4; i_++) {                                       \
            int r_ = lr + 32 * i_;                                             \
            uint32_t off = SW128(r_ * 128 + ls * 16);                          \
            CP16(ab + off, &Ab[(size_t)(q0 + r_) * KQK + kb]);                 \
            CP16(bb + off, &Bb[(size_t)(c0 + r_) * KQK + kb]);                 \
        }                                                                      \
        CP_COMMIT();                                                           \
    } while (0)

    float acc[4][4][4] = {};
    SC_LOAD(0, 0);
    for (int c = 0; c < 3; c++) {
        const int st = c & 1;
        if (c + 1 < 3) {
            SC_LOAD(c + 1, st ^ 1);
            asm volatile("cp.async.wait_group 1;");
        } else {
            asm volatile("cp.async.wait_group 0;");
        }
        __syncthreads();
        const uint32_t abase = sb + st * 16384;
        const uint32_t bbase = sb + 32768 + st * 16384;
#pragma unroll
        for (int ks = 0; ks < 4; ks++) {
            uint32_t af[4][4];
#pragma unroll
            for (int mt = 0; mt < 4; mt++) {
                int row = warp_m * 64 + mt * 16 + (lane & 15);
                int seg = ks * 2 + (lane >> 4);
                ldm_x4(af[mt], abase + SW128(row * 128 + seg * 16));
            }
            uint32_t bf[2][4];
#pragma unroll
            for (int h = 0; h < 2; h++) {
                int row = warp_n * 32 + h * 16 + ((lane >> 4) & 1) * 8 + (lane & 7);
                int seg = ks * 2 + ((lane >> 3) & 1);
                ldm_x4(bf[h], bbase + SW128(row * 128 + seg * 16));
            }
#pragma unroll
            for (int mt = 0; mt < 4; mt++)
#pragma unroll
                for (int nt = 0; nt < 4; nt++)
                    mma_bf16(acc[mt][nt], af[mt],
                             bf[nt >> 1][(nt & 1) * 2], bf[nt >> 1][(nt & 1) * 2 + 1]);
        }
        __syncthreads();
    }
#undef SC_LOAD

    float* Arow = attn + (size_t)bh * S_LEN * S_LEN;
    const int mrow = lane >> 2;
    const int ncol = 2 * (lane & 3);
#pragma unroll
    for (int mt = 0; mt < 4; mt++)
#pragma unroll
        for (int nt = 0; nt < 4; nt++) {
            int cg = c0 + warp_n * 32 + nt * 8 + ncol;
#pragma unroll
            for (int half = 0; half < 2; half++) {
                int q = q0 + warp_m * 64 + mt * 16 + mrow + half * 8;
                float2 v = {acc[mt][nt][half * 2] * 0.125f,
                            acc[mt][nt][half * 2 + 1] * 0.125f};
                *(float2*)&Arow[(size_t)q * S_LEN + cg] = v;
            }
        }
}

// ---------------------------------------------------------------------------
// Row-wise causal softmax; writes fp32 probs (full row) + bf16 hi/lo planes.
// ---------------------------------------------------------------------------
__global__ __launch_bounds__(256) void softmax_kernel(
    float* __restrict__ attn, __nv_bfloat16* __restrict__ Ph,
    __nv_bfloat16* __restrict__ Pl)
{
    const int q = blockIdx.x, bh = blockIdx.y;
    const size_t rbase = ((size_t)bh * S_LEN + q) * S_LEN;
    float* row = attn + rbase;
    const int tid = threadIdx.x;
    const int valid = q + 1;
    const int b0 = 4 * tid, b1 = 4 * (tid + 256);

    float4 v0 = {-INFINITY, -INFINITY, -INFINITY, -INFINITY}, v1 = v0;
    if (b0 < valid) v0 = *(const float4*)&row[b0];
    if (b1 < valid) v1 = *(const float4*)&row[b1];
    float vals[8] = {v0.x, v0.y, v0.z, v0.w, v1.x, v1.y, v1.z, v1.w};

    float mx = -INFINITY;
#pragma unroll
    for (int i = 0; i < 8; i++) {
        int k = (i < 4) ? (b0 + i) : (b1 + i - 4);
        if (k >= valid) vals[i] = -INFINITY;
        mx = fmaxf(mx, vals[i]);
    }
#pragma unroll
    for (int o = 16; o; o >>= 1) mx = fmaxf(mx, __shfl_xor_sync(~0u, mx, o));
    __shared__ float sred[8];
    if ((tid & 31) == 0) sred[tid >> 5] = mx;
    __syncthreads();
    mx = sred[0];
#pragma unroll
    for (int i = 1; i < 8; i++) mx = fmaxf(mx, sred[i]);
    __syncthreads();

    float sum = 0.f;
#pragma unroll
    for (int i = 0; i < 8; i++) {
        float e = __expf(vals[i] - mx);
        vals[i] = e;
        sum += e;
    }
#pragma unroll
    for (int o = 16; o; o >>= 1) sum += __shfl_xor_sync(~0u, sum, o);
    if ((tid & 31) == 0) sred[tid >> 5] = sum;
    __syncthreads();
    sum = 0.f;
#pragma unroll
    for (int i = 0; i < 8; i++) sum += sred[i];
    const float inv = 1.f / sum;

    float p[8];
    __nv_bfloat16 hh[8], ll[8];
#pragma unroll
    for (int i = 0; i < 8; i++) {
        p[i] = vals[i] * inv;
        hh[i] = __float2bfloat16(p[i]);
        ll[i] = __float2bfloat16(p[i] - __bfloat162float(hh[i]));
    }
    float4 w0 = {p[0], p[1], p[2], p[3]};
    float4 w1 = {p[4], p[5], p[6], p[7]};
    *(float4*)&row[b0] = w0;
    *(float4*)&row[b1] = w1;
#pragma unroll
    for (int j = 0; j < 2; j++) {
        *(__nv_bfloat162*)&Ph[rbase + b0 + 2*j] = __halves2bfloat162(hh[2*j], hh[2*j+1]);
        *(__nv_bfloat162*)&Ph[rbase + b1 + 2*j] = __halves2bfloat162(hh[4+2*j], hh[5+2*j]);
        *(__nv_bfloat162*)&Pl[rbase + b0 + 2*j] = __halves2bfloat162(ll[2*j], ll[2*j+1]);
        *(__nv_bfloat162*)&Pl[rbase + b1 + 2*j] = __halves2bfloat162(ll[4+2*j], ll[5+2*j]);
    }
}

// ---------------------------------------------------------------------------
// av_mma: A[q,hd] = sum_k P[q,k]*V[k,hd] via Ph*Vh + Pl*Vh + Ph*Vl.
// 128(q) x 64(hd) tile; causal chunk bound. Writes A in split-cat layout.
// Stage layout: Ph 0, Pl 16K, Vh 32K, Vl 40K; stage size 48K, 2 stages.
// ---------------------------------------------------------------------------
#define AV_SMEM 98304

__global__ __launch_bounds__(256) void av_mma(
    const __nv_bfloat16* __restrict__ Ph, const __nv_bfloat16* __restrict__ Pl,
    const __nv_bfloat16* __restrict__ Vth, const __nv_bfloat16* __restrict__ Vtl,
    __nv_bfloat16* __restrict__ Acat)
{
    const int qt = blockIdx.x, bh = blockIdx.y;
    extern __shared__ __align__(1024) char smem[];
    const int tid = threadIdx.x;
    const int wid = tid >> 5, lane = tid & 31;
    const int warp_m = wid & 3;           // 32 q rows each
    const int warp_n = wid >> 2;          // 32 hd cols each
    const uint32_t sb = smem_u32(smem);
    const int q0 = qt * 128;

    const __nv_bfloat16* Phb = Ph + (size_t)bh * S_LEN * S_LEN;
    const __nv_bfloat16* Plb = Pl + (size_t)bh * S_LEN * S_LEN;
    const __nv_bfloat16* Vhb = Vth + (size_t)bh * HD * S_LEN;
    const __nv_bfloat16* Vlb = Vtl + (size_t)bh * HD * S_LEN;

    const int ls = tid & 7;
    const int lr = tid >> 3;
    const int nch = (q0 + 128) / 64;

#define AV_LOAD(chunk, stage) do {                                             \
        uint32_t base = sb + (stage) * 49152;                                  \
        size_t kb = (size_t)(chunk) * 64 + ls * 8;                             \
        _Pragma("unroll")                                                      \
        for (int i_ = 0; i_ < 4; i_++) {                                       \
            int r_ = lr + 32 * i_;                                             \
            uint32_t off = SW128(r_ * 128 + ls * 16);                          \
            CP16(base + off,         &Phb[(size_t)(q0 + r_) * S_LEN + kb]);    \
            CP16(base + 16384 + off, &Plb[(size_t)(q0 + r_) * S_LEN + kb]);    \
        }                                                                      \
        _Pragma("unroll")                                                      \
        for (int i_ = 0; i_ < 2; i_++) {                                       \
            int r_ = lr + 32 * i_;                                             \
            uint32_t off = SW128(r_ * 128 + ls * 16);                          \
            CP16(base + 32768 + off, &Vhb[(size_t)r_ * S_LEN + kb]);           \
            CP16(base + 40960 + off, &Vlb[(size_t)r_ * S_LEN + kb]);           \
        }                                                                      \
        CP_COMMIT();                                                           \
    } while (0)

    float acc[2][4][4] = {};   // [mt 16q][nt 8hd]
    AV_LOAD(0, 0);
    for (int c = 0; c < nch; c++) {
        const int st = c & 1;
        if (c + 1 < nch) {
            AV_LOAD(c + 1, st ^ 1);
            asm volatile("cp.async.wait_group 1;");
        } else {
            asm volatile("cp.async.wait_group 0;");
        }
        __syncthreads();
        const uint32_t base = sb + st * 49152;
#pragma unroll
        for (int ks = 0; ks < 4; ks++) {
            uint32_t ah[2][4], al[2][4];
#pragma unroll
            for (int mt = 0; mt < 2; mt++) {
                int row = warp_m * 32 + mt * 16 + (lane & 15);
                int seg = ks * 2 + (lane >> 4);
                uint32_t off = SW128(row * 128 + seg * 16);
                ldm_x4(ah[mt], base + off);
                ldm_x4(al[mt], base + 16384 + off);
            }
            uint32_t bh_[2][4], bl_[2][4];
#pragma unroll
            for (int h = 0; h < 2; h++) {
                int row = warp_n * 32 + h * 16 + ((lane >> 4) & 1) * 8 + (lane & 7);
                int seg = ks * 2 + ((lane >> 3) & 1);
                uint32_t off = SW128(row * 128 + seg * 16);
                ldm_x4(bh_[h], base + 32768 + off);
                ldm_x4(bl_[h], base + 40960 + off);
            }
#pragma unroll
            for (int mt = 0; mt < 2; mt++)
#pragma unroll
                for (int nt = 0; nt < 4; nt++) {
                    uint32_t bh0 = bh_[nt >> 1][(nt & 1) * 2];
                    uint32_t bh1 = bh_[nt >> 1][(nt & 1) * 2 + 1];
                    uint32_t bl0 = bl_[nt >> 1][(nt & 1) * 2];
                    uint32_t bl1 = bl_[nt >> 1][(nt & 1) * 2 + 1];
                    mma_bf16(acc[mt][nt], ah[mt], bh0, bh1);
                    mma_bf16(acc[mt][nt], al[mt], bh0, bh1);
                    mma_bf16(acc[mt][nt], ah[mt], bl0, bl1);
                }
        }
        __syncthreads();
    }
#undef AV_LOAD

    // epilogue: write A in split-cat layout [hi,hi,lo] for the Wo GEMM
    const int bb = bh / NH, h = bh % NH;
    const int mrow = lane >> 2;
    const int ncol = 2 * (lane & 3);
#pragma unroll
    for (int mt = 0; mt < 2; mt++)
#pragma unroll
        for (int nt = 0; nt < 4; nt++) {
            int hd = warp_n * 32 + nt * 8 + ncol;
            int cc = h * HD + hd;
#pragma unroll
            for (int half = 0; half < 2; half++) {
                int s = q0 + warp_m * 32 + mt * 16 + mrow + half * 8;
                float v0 = acc[mt][nt][half * 2];
                float v1 = acc[mt][nt][half * 2 + 1];
                __nv_bfloat16 h0 = __float2bfloat16(v0);
                __nv_bfloat16 h1 = __float2bfloat16(v1);
                __nv_bfloat16 l0 = __float2bfloat16(v0 - __bfloat162float(h0));
                __nv_bfloat16 l1 = __float2bfloat16(v1 - __bfloat162float(h1));
                size_t base = ((size_t)(bb * S_LEN + s)) * KCAT + cc;
                *(__nv_bfloat162*)&Acat[base]          = __halves2bfloat162(h0, h1);
                *(__nv_bfloat162*)&Acat[base + DM]     = __halves2bfloat162(h0, h1);
                *(__nv_bfloat162*)&Acat[base + 2 * DM] = __halves2bfloat162(l0, l1);
            }
        }
}

// ---------------------------------------------------------------------------
extern "C" void kernel_launch(void* const* d_in, const int* in_sizes, int n_in,
                              void* d_out, int out_size)
{
    const float* X  = (const float*)d_in[0];
    const float* Wq = (const float*)d_in[1];
    const float* bq = (const float*)d_in[2];
    const float* Wk = (const float*)d_in[3];
    const float* bk = (const float*)d_in[4];
    const float* Wv = (const float*)d_in[5];
    const float* bv = (const float*)d_in[6];
    const float* Wo = (const float*)d_in[7];
    const float* bo = (const float*)d_in[8];

    float* out  = (float*)d_out;
    float* attn = out + (size_t)MROWS * DM;

    __nv_bfloat16 *gXc, *gAc, *gWq, *gWk, *gWv, *gWo;
    __nv_bfloat16 *gQc, *gKc, *gVh, *gVl, *gPh, *gPl;
    cudaGetSymbolAddress((void**)&gXc, g_Xcat);
    cudaGetSymbolAddress((void**)&gAc, g_Acat);
    cudaGetSymbolAddress((void**)&gWq, g_Wqc);
    cudaGetSymbolAddress((void**)&gWk, g_Wkc);
    cudaGetSymbolAddress((void**)&gWv, g_Wvc);
    cudaGetSymbolAddress((void**)&gWo, g_Woc);
    cudaGetSymbolAddress((void**)&gQc, g_Qc);
    cudaGetSymbolAddress((void**)&gKc, g_Kc);
    cudaGetSymbolAddress((void**)&gVh, g_Vth);
    cudaGetSymbolAddress((void**)&gVl, g_Vtl);
    cudaGetSymbolAddress((void**)&gPh, g_Ph);
    cudaGetSymbolAddress((void**)&gPl, g_Pl);

    static int smem_set = 0;
    if (!smem_set) {
        cudaFuncSetAttribute(gemm_mma, cudaFuncAttributeMaxDynamicSharedMemorySize, GEMM_SMEM);
        cudaFuncSetAttribute(scores_mma, cudaFuncAttributeMaxDynamicSharedMemorySize, SC_SMEM);
        cudaFuncSetAttribute(av_mma, cudaFuncAttributeMaxDynamicSharedMemorySize, AV_SMEM);
        smem_set = 1;
    }

    dim3 blk(256);
    convert_cat<<<512, blk>>>(Wq, gWq, DM, 1);
    convert_cat<<<512, blk>>>(Wk, gWk, DM, 1);
    convert_cat<<<512, blk>>>(Wv, gWv, DM, 1);
    convert_cat<<<512, blk>>>(Wo, gWo, DM, 1);
    convert_cat<<<1024, blk>>>(X, gXc, MROWS, 0);

    dim3 ggemm(DM / 128, MROWS / 128);
    gemm_mma<<<ggemm, blk, GEMM_SMEM>>>(gXc, gWq, bq, nullptr, gQc, nullptr, 1);
    gemm_mma<<<ggemm, blk, GEMM_SMEM>>>(gXc, gWk, bk, nullptr, gKc, nullptr, 2);
    gemm_mma<<<ggemm, blk, GEMM_SMEM>>>(gXc, gWv, bv, nullptr, gVh, gVl, 3);

    dim3 gsc(S_LEN / 128, S_LEN / 128, BHN);
    scores_mma<<<gsc, blk, SC_SMEM>>>(gQc, gKc, attn);

    dim3 gsm(S_LEN, BHN);
    softmax_kernel<<<gsm, blk>>>(attn, gPh, gPl);

    dim3 gav(S_LEN / 128, BHN);
    av_mma<<<gav, blk, AV_SMEM>>>(gPh, gPl, gVh, gVl, gAc);

    gemm_mma<<<ggemm, blk, GEMM_SMEM>>>(gAc, gWo, bo, out, nullptr, nullptr, 0);
}